// round 16
// baseline (speedup 1.0000x reference)
#include <cuda_runtime.h>
#include <math.h>

// Problem dims (fixed by dataset)
#define F_IN 64
#define HC   128   // H*C
#define H    4
#define C    32
#define MAXN 50000
#define MAXE 800000

// ---------------- scratch (static device memory; no allocation) ----------------
// INVARIANT: g_deg is all-zero at entry to kernel_launch (static init for call 1;
// the scatter part re-zeroes it each run, restoring the invariant).
__device__ float g_xl[(size_t)MAXN * HC];
__device__ float g_xr[(size_t)MAXN * HC];
__device__ float g_xl2[MAXN];
__device__ float g_xr2[MAXN];
__device__ int   g_deg[MAXN];
__device__ int   g_rowptr[MAXN + 1];
__device__ int   g_col[MAXE];
__device__ int   g_slot[MAXE];     // edge's slot within its dst segment (from hist atomic)

// ---------------- warp all-reduce sum (shfl tree) ----------------
__device__ __forceinline__ float warp_sum(float v) {
    #pragma unroll
    for (int o = 16; o > 0; o >>= 1) v += __shfl_xor_sync(0xffffffffu, v, o);
    return v;
}

// ---------------- histogram: count degrees AND record each edge's slot ----------------
__global__ __launch_bounds__(256) void hist_k(const int* __restrict__ ei, int E) {
    int t      = blockIdx.x * 256 + threadIdx.x;
    int stride = gridDim.x * 256;
    if ((E & 3) == 0) {
        const int4* d4 = reinterpret_cast<const int4*>(ei + E);
        int n4 = E >> 2;
        for (int i = t; i < n4; i += stride) {
            int4 v = __ldg(&d4[i]);
            int4 sl;
            sl.x = atomicAdd(&g_deg[v.x], 1);
            sl.y = atomicAdd(&g_deg[v.y], 1);
            sl.z = atomicAdd(&g_deg[v.z], 1);
            sl.w = atomicAdd(&g_deg[v.w], 1);
            reinterpret_cast<int4*>(g_slot)[i] = sl;
        }
    } else {
        for (int e = t; e < E; e += stride)
            g_slot[e] = atomicAdd(&g_deg[ei[E + e]], 1);
    }
}

// ---------------- merged exclusive scan: each block self-computes its prefix ----------------
__global__ __launch_bounds__(256) void scan_k(int N, int nsb) {
    int b   = blockIdx.x;
    int tid = threadIdx.x;
    int lane = tid & 31, wid = tid >> 5;

    // 1) prefix offset: parallel sum of the preceding region
    int pre = 0;
    for (int i = tid; i < b * 256; i += 256) pre += g_deg[i];

    // 2) own value + intra-block inclusive scan
    int idx = b * 256 + tid;
    int v   = (idx < N) ? g_deg[idx] : 0;

    int incl = v;
    #pragma unroll
    for (int o = 1; o < 32; o <<= 1) {
        int t = __shfl_up_sync(0xffffffffu, incl, o);
        if (lane >= o) incl += t;
    }
    #pragma unroll
    for (int o = 16; o > 0; o >>= 1) pre += __shfl_xor_sync(0xffffffffu, pre, o);

    __shared__ int ws[8], wp[8];
    if (lane == 31) ws[wid] = incl;
    if (lane == 0)  wp[wid] = pre;
    __syncthreads();
    __shared__ int s_off;
    if (tid < 8) {
        int t = ws[tid];
        #pragma unroll
        for (int o = 1; o < 8; o <<= 1) {
            int u = __shfl_up_sync(0xffu, t, o);
            if (tid >= o) t += u;
        }
        ws[tid] = t;
        if (tid == 0) {
            int P = 0;
            #pragma unroll
            for (int k = 0; k < 8; k++) P += wp[k];
            s_off = P;
        }
    }
    __syncthreads();
    int excl = incl - v + (wid ? ws[wid - 1] : 0);
    int off  = s_off;

    if (idx < N) g_rowptr[idx] = excl + off;
    if (b == nsb - 1 && tid == 255) g_rowptr[N] = off + excl + v;
}

// ---------------- fused SCATTER + GEMM (independent work, overlapped) ----------------
__global__ __launch_bounds__(256) void scatter_gemm_k(const float* __restrict__ x,
                                                      const float* __restrict__ Wl,
                                                      const float* __restrict__ Wr,
                                                      const int* __restrict__ ei,
                                                      int N, int E, int gemm_blocks) {
    __shared__ float sW[F_IN * HC];   // 32 KB
    __shared__ float sx[64 * F_IN];   // 16 KB
    int tid = threadIdx.x;

    if (blockIdx.x >= gemm_blocks) {
        // ---- scatter part ----
        int sb     = blockIdx.x - gemm_blocks;
        int nsb    = gridDim.x - gemm_blocks;
        int t      = sb * 256 + tid;
        int stride = nsb * 256;
        for (int e = t; e < E; e += stride) {
            int s  = __ldg(&ei[e]);
            int d  = __ldg(&ei[E + e]);
            int sl = __ldg(&g_slot[e]);
            g_col[__ldg(&g_rowptr[d]) + sl] = s;
        }
        // restore the g_deg == 0 invariant for the next kernel_launch/replay
        for (int i = t; i < N; i += stride) g_deg[i] = 0;
        return;
    }

    // ---- GEMM part ----
    int base = blockIdx.x * 64;
    for (int i = tid; i < 64 * F_IN / 4; i += 256) {
        int n  = i >> 4;
        int k4 = i & 15;
        int node = base + n;
        float4 v = make_float4(0.f, 0.f, 0.f, 0.f);
        if (node < N) v = reinterpret_cast<const float4*>(x + (size_t)node * F_IN)[k4];
        ((float4*)sx)[i] = v;
    }

    int cg = tid & 31;
    int ng = tid >> 5;

    #pragma unroll
    for (int which = 0; which < 2; which++) {
        const float* W = which ? Wr : Wl;
        __syncthreads();
        for (int i = tid; i < F_IN * HC / 4; i += 256)
            ((float4*)sW)[i] = ((const float4*)W)[i];
        __syncthreads();

        float acc[8][4];
        #pragma unroll
        for (int n = 0; n < 8; n++)
            #pragma unroll
            for (int q = 0; q < 4; q++) acc[n][q] = 0.f;

        #pragma unroll
        for (int k = 0; k < F_IN; k++) {
            float4 w = *reinterpret_cast<float4*>(&sW[k * HC + cg * 4]);
            #pragma unroll
            for (int n = 0; n < 8; n++) {
                float xv = sx[(ng * 8 + n) * F_IN + k];
                acc[n][0] += xv * w.x;
                acc[n][1] += xv * w.y;
                acc[n][2] += xv * w.z;
                acc[n][3] += xv * w.w;
            }
        }

        float* outp = which ? g_xr : g_xl;
        #pragma unroll
        for (int n = 0; n < 8; n++) {
            int node = base + ng * 8 + n;
            if (node < N) {
                float4 v = make_float4(acc[n][0], acc[n][1], acc[n][2], acc[n][3]);
                *reinterpret_cast<float4*>(&outp[(size_t)node * HC + cg * 4]) = v;
            }
        }
    }
}

// ---------------- Layer 1: one warp per dst, 64-thread blocks (2 dsts/block),
// |t| identity: leaky(t) = 0.6t + 0.4|t| -> dot is 8 FFMA with free FABS modifier ----------------
__device__ __forceinline__ void edge_step(int src, int lane,
                                          const float4 xr4,
                                          const float4 a06, const float4 a04,
                                          float& s, float4& A) {
    const float4 v = __ldg(&reinterpret_cast<const float4*>(g_xl)[(size_t)src * (HC / 4) + lane]);
    float tx = v.x + xr4.x;
    float ty = v.y + xr4.y;
    float tz = v.z + xr4.z;
    float tw = v.w + xr4.w;
    float e = a06.x * tx + a04.x * fabsf(tx)
            + a06.y * ty + a04.y * fabsf(ty)
            + a06.z * tz + a04.z * fabsf(tz)
            + a06.w * tw + a04.w * fabsf(tw);
    e += __shfl_xor_sync(0xffffffffu, e, 4);
    e += __shfl_xor_sync(0xffffffffu, e, 2);
    e += __shfl_xor_sync(0xffffffffu, e, 1);
    float p = __expf(e);
    s += p;
    A.x += p * v.x; A.y += p * v.y; A.z += p * v.z; A.w += p * v.w;
}

__global__ __launch_bounds__(64, 20) void agg1_k(const float* __restrict__ att1,
                                                 const float* __restrict__ b1,
                                                 const float* __restrict__ Wl2,
                                                 const float* __restrict__ Wr2,
                                                 int N) {
    int dst  = blockIdx.x * 2 + (threadIdx.x >> 5);
    int lane = threadIdx.x & 31;
    if (dst >= N) return;

    const float4 xr4 = reinterpret_cast<const float4*>(g_xr)[(size_t)dst * (HC / 4) + lane];
    const float4 a4  = __ldg(&reinterpret_cast<const float4*>(att1)[lane]);
    float4 a06 = make_float4(0.6f * a4.x, 0.6f * a4.y, 0.6f * a4.z, 0.6f * a4.w);
    float4 a04 = make_float4(0.4f * a4.x, 0.4f * a4.y, 0.4f * a4.z, 0.4f * a4.w);

    int beg = g_rowptr[dst];
    int end = g_rowptr[dst + 1];

    float  s0 = 0.f, s1 = 0.f;
    float4 A0 = {0,0,0,0}, A1 = {0,0,0,0};

    // self loop
    edge_step(dst, lane, xr4, a06, a04, s0, A0);

    int j = beg;
    for (; j + 2 <= end; j += 2) {
        int i0 = __ldg(&g_col[j]);
        int i1 = __ldg(&g_col[j + 1]);
        edge_step(i0, lane, xr4, a06, a04, s0, A0);
        edge_step(i1, lane, xr4, a06, a04, s1, A1);
    }
    if (j < end)
        edge_step(__ldg(&g_col[j]), lane, xr4, a06, a04, s0, A0);

    float s = s0 + s1;
    float4 A;
    A.x = A0.x + A1.x;
    A.y = A0.y + A1.y;
    A.z = A0.z + A1.z;
    A.w = A0.w + A1.w;

    const float4 b4  = __ldg(&reinterpret_cast<const float4*>(b1)[lane]);
    const float4 wl4 = __ldg(&reinterpret_cast<const float4*>(Wl2)[lane]);
    const float4 wr4 = __ldg(&reinterpret_cast<const float4*>(Wr2)[lane]);

    float inv = 1.f / s;
    float ox = A.x * inv + b4.x;
    float oy = A.y * inv + b4.y;
    float oz = A.z * inv + b4.z;
    float ow = A.w * inv + b4.w;
    float hx = (ox > 0.f) ? ox : expm1f(ox);
    float hy = (oy > 0.f) ? oy : expm1f(oy);
    float hz = (oz > 0.f) ? oz : expm1f(oz);
    float hw = (ow > 0.f) ? ow : expm1f(ow);

    float l2 = warp_sum(hx * wl4.x + hy * wl4.y + hz * wl4.z + hw * wl4.w);
    float r2 = warp_sum(hx * wr4.x + hy * wr4.y + hz * wr4.z + hw * wr4.w);
    if (lane == 0) {
        g_xl2[dst] = l2;
        g_xr2[dst] = r2;
    }
}

// ---------------- Layer 2: 8-lane segments, 4 dsts per warp ----------------
__global__ __launch_bounds__(256) void agg2_k(const float* __restrict__ att2,
                                              const float* __restrict__ b2,
                                              float* __restrict__ out, int N) {
    int warpid = blockIdx.x * (blockDim.x >> 5) + (threadIdx.x >> 5);
    int lane = threadIdx.x & 31;
    int sub  = lane >> 3;
    int l8   = lane & 7;
    int dst0 = warpid * 4 + sub;
    int dst  = (dst0 < N) ? dst0 : (N - 1);

    float xr = g_xr2[dst];
    float a  = att2[0];
    int beg = g_rowptr[dst];
    int end = g_rowptr[dst + 1];

    float s = 0.f, w = 0.f;

    for (int j = beg + l8; j <= end; j += 8) {
        int src = (j < end) ? __ldg(&g_col[j]) : dst;
        float l = g_xl2[src];
        float t = l + xr;
        t = (t >= 0.f) ? t : 0.2f * t;
        float p = __expf(a * t);
        s += p;
        w += p * l;
    }

    s += __shfl_xor_sync(0xffffffffu, s, 4);
    s += __shfl_xor_sync(0xffffffffu, s, 2);
    s += __shfl_xor_sync(0xffffffffu, s, 1);
    w += __shfl_xor_sync(0xffffffffu, w, 4);
    w += __shfl_xor_sync(0xffffffffu, w, 2);
    w += __shfl_xor_sync(0xffffffffu, w, 1);

    if (l8 == 0 && dst0 < N) out[dst0] = w / s + b2[0];
}

// ---------------- launch ----------------
extern "C" void kernel_launch(void* const* d_in, const int* in_sizes, int n_in,
                              void* d_out, int out_size) {
    const float* x    = (const float*)d_in[0];
    const int*   ei   = (const int*)d_in[1];     // int32 (verified)
    const float* Wl1  = (const float*)d_in[2];
    const float* Wr1  = (const float*)d_in[3];
    const float* att1 = (const float*)d_in[4];
    const float* b1   = (const float*)d_in[5];
    const float* Wl2  = (const float*)d_in[6];
    const float* Wr2  = (const float*)d_in[7];
    const float* att2 = (const float*)d_in[8];
    const float* b2   = (const float*)d_in[9];
    float*       out  = (float*)d_out;

    int N = in_sizes[0] / F_IN;
    int E = in_sizes[1] / 2;
    int nsb = (N + 255) / 256;
    int gemm_blocks = (N + 63) / 64;
    int scat_blocks = (E + 1023) / 1024;

    hist_k<<<(E / 4 + 255) / 256, 256>>>(ei, E);
    scan_k<<<nsb, 256>>>(N, nsb);
    scatter_gemm_k<<<gemm_blocks + scat_blocks, 256>>>(x, Wl1, Wr1, ei, N, E, gemm_blocks);
    agg1_k<<<(N + 1) / 2, 64>>>(att1, b1, Wl2, Wr2, N);
    agg2_k<<<(N + 31) / 32, 256>>>(att2, b2, out, N);
}

// round 17
// speedup vs baseline: 1.0812x; 1.0812x over previous
#include <cuda_runtime.h>
#include <math.h>

// Problem dims (fixed by dataset)
#define F_IN 64
#define HC   128   // H*C
#define H    4
#define C    32
#define MAXN 50000
#define MAXE 800000

// ---------------- scratch (static device memory; no allocation) ----------------
// INVARIANT: g_deg is all-zero at entry to kernel_launch (static init for call 1;
// the scatter part re-zeroes it each run, restoring the invariant).
__device__ float g_xl[(size_t)MAXN * HC];
__device__ float g_xr[(size_t)MAXN * HC];
__device__ float g_xl2[MAXN];
__device__ float g_xr2[MAXN];
__device__ int   g_deg[MAXN];
__device__ int   g_rowptr[MAXN + 1];
__device__ int   g_col[MAXE];
__device__ int   g_slot[MAXE];     // edge's slot within its dst segment (from hist atomic)

// ---------------- warp all-reduce sum (shfl tree) ----------------
__device__ __forceinline__ float warp_sum(float v) {
    #pragma unroll
    for (int o = 16; o > 0; o >>= 1) v += __shfl_xor_sync(0xffffffffu, v, o);
    return v;
}

// ---------------- histogram: count degrees AND record each edge's slot ----------------
__global__ __launch_bounds__(256) void hist_k(const int* __restrict__ ei, int E) {
    int t      = blockIdx.x * 256 + threadIdx.x;
    int stride = gridDim.x * 256;
    if ((E & 3) == 0) {
        const int4* d4 = reinterpret_cast<const int4*>(ei + E);
        int n4 = E >> 2;
        for (int i = t; i < n4; i += stride) {
            int4 v = __ldg(&d4[i]);
            int4 sl;
            sl.x = atomicAdd(&g_deg[v.x], 1);
            sl.y = atomicAdd(&g_deg[v.y], 1);
            sl.z = atomicAdd(&g_deg[v.z], 1);
            sl.w = atomicAdd(&g_deg[v.w], 1);
            reinterpret_cast<int4*>(g_slot)[i] = sl;
        }
    } else {
        for (int e = t; e < E; e += stride)
            g_slot[e] = atomicAdd(&g_deg[ei[E + e]], 1);
    }
}

// ---------------- merged exclusive scan: each block self-computes its prefix ----------------
__global__ __launch_bounds__(256) void scan_k(int N, int nsb) {
    int b   = blockIdx.x;
    int tid = threadIdx.x;
    int lane = tid & 31, wid = tid >> 5;

    // 1) prefix offset: parallel sum of the preceding region
    int pre = 0;
    for (int i = tid; i < b * 256; i += 256) pre += g_deg[i];

    // 2) own value + intra-block inclusive scan
    int idx = b * 256 + tid;
    int v   = (idx < N) ? g_deg[idx] : 0;

    int incl = v;
    #pragma unroll
    for (int o = 1; o < 32; o <<= 1) {
        int t = __shfl_up_sync(0xffffffffu, incl, o);
        if (lane >= o) incl += t;
    }
    #pragma unroll
    for (int o = 16; o > 0; o >>= 1) pre += __shfl_xor_sync(0xffffffffu, pre, o);

    __shared__ int ws[8], wp[8];
    if (lane == 31) ws[wid] = incl;
    if (lane == 0)  wp[wid] = pre;
    __syncthreads();
    __shared__ int s_off;
    if (tid < 8) {
        int t = ws[tid];
        #pragma unroll
        for (int o = 1; o < 8; o <<= 1) {
            int u = __shfl_up_sync(0xffu, t, o);
            if (tid >= o) t += u;
        }
        ws[tid] = t;
        if (tid == 0) {
            int P = 0;
            #pragma unroll
            for (int k = 0; k < 8; k++) P += wp[k];
            s_off = P;
        }
    }
    __syncthreads();
    int excl = incl - v + (wid ? ws[wid - 1] : 0);
    int off  = s_off;

    if (idx < N) g_rowptr[idx] = excl + off;
    if (b == nsb - 1 && tid == 255) g_rowptr[N] = off + excl + v;
}

// ---------------- fused SCATTER + GEMM (independent work, overlapped) ----------------
__global__ __launch_bounds__(256) void scatter_gemm_k(const float* __restrict__ x,
                                                      const float* __restrict__ Wl,
                                                      const float* __restrict__ Wr,
                                                      const int* __restrict__ ei,
                                                      int N, int E, int gemm_blocks) {
    __shared__ float sW[F_IN * HC];   // 32 KB
    __shared__ float sx[64 * F_IN];   // 16 KB
    int tid = threadIdx.x;

    if (blockIdx.x >= gemm_blocks) {
        // ---- scatter part ----
        int sb     = blockIdx.x - gemm_blocks;
        int nsb    = gridDim.x - gemm_blocks;
        int t      = sb * 256 + tid;
        int stride = nsb * 256;
        for (int e = t; e < E; e += stride) {
            int s  = __ldg(&ei[e]);
            int d  = __ldg(&ei[E + e]);
            int sl = __ldg(&g_slot[e]);
            g_col[__ldg(&g_rowptr[d]) + sl] = s;
        }
        // restore the g_deg == 0 invariant for the next kernel_launch/replay
        for (int i = t; i < N; i += stride) g_deg[i] = 0;
        return;
    }

    // ---- GEMM part ----
    int base = blockIdx.x * 64;
    for (int i = tid; i < 64 * F_IN / 4; i += 256) {
        int n  = i >> 4;
        int k4 = i & 15;
        int node = base + n;
        float4 v = make_float4(0.f, 0.f, 0.f, 0.f);
        if (node < N) v = reinterpret_cast<const float4*>(x + (size_t)node * F_IN)[k4];
        ((float4*)sx)[i] = v;
    }

    int cg = tid & 31;
    int ng = tid >> 5;

    #pragma unroll
    for (int which = 0; which < 2; which++) {
        const float* W = which ? Wr : Wl;
        __syncthreads();
        for (int i = tid; i < F_IN * HC / 4; i += 256)
            ((float4*)sW)[i] = ((const float4*)W)[i];
        __syncthreads();

        float acc[8][4];
        #pragma unroll
        for (int n = 0; n < 8; n++)
            #pragma unroll
            for (int q = 0; q < 4; q++) acc[n][q] = 0.f;

        #pragma unroll
        for (int k = 0; k < F_IN; k++) {
            float4 w = *reinterpret_cast<float4*>(&sW[k * HC + cg * 4]);
            #pragma unroll
            for (int n = 0; n < 8; n++) {
                float xv = sx[(ng * 8 + n) * F_IN + k];
                acc[n][0] += xv * w.x;
                acc[n][1] += xv * w.y;
                acc[n][2] += xv * w.z;
                acc[n][3] += xv * w.w;
            }
        }

        float* outp = which ? g_xr : g_xl;
        #pragma unroll
        for (int n = 0; n < 8; n++) {
            int node = base + ng * 8 + n;
            if (node < N) {
                float4 v = make_float4(acc[n][0], acc[n][1], acc[n][2], acc[n][3]);
                *reinterpret_cast<float4*>(&outp[(size_t)node * HC + cg * 4]) = v;
            }
        }
    }
}

// ---------------- Layer 1: one 32-thread CTA per destination, 4-way interleave (R15 proven),
// |t| identity: leaky(t)*a = a06*t + a04*|t| (FABS folds into FFMA operand) ----------------
__device__ __forceinline__ void edge_step(int src, int lane,
                                          const float4 xr4,
                                          const float4 a06, const float4 a04,
                                          float& s, float4& A) {
    const float4 v = __ldg(&reinterpret_cast<const float4*>(g_xl)[(size_t)src * (HC / 4) + lane]);
    float tx = v.x + xr4.x;
    float ty = v.y + xr4.y;
    float tz = v.z + xr4.z;
    float tw = v.w + xr4.w;
    float e = a06.x * tx + a04.x * fabsf(tx)
            + a06.y * ty + a04.y * fabsf(ty)
            + a06.z * tz + a04.z * fabsf(tz)
            + a06.w * tw + a04.w * fabsf(tw);
    e += __shfl_xor_sync(0xffffffffu, e, 4);
    e += __shfl_xor_sync(0xffffffffu, e, 2);
    e += __shfl_xor_sync(0xffffffffu, e, 1);
    float p = __expf(e);
    s += p;
    A.x += p * v.x; A.y += p * v.y; A.z += p * v.z; A.w += p * v.w;
}

__global__ __launch_bounds__(32) void agg1_k(const float* __restrict__ att1,
                                             const float* __restrict__ b1,
                                             const float* __restrict__ Wl2,
                                             const float* __restrict__ Wr2,
                                             int N) {
    int dst  = blockIdx.x;
    int lane = threadIdx.x;

    const float4 xr4 = reinterpret_cast<const float4*>(g_xr)[(size_t)dst * (HC / 4) + lane];
    const float4 a4  = __ldg(&reinterpret_cast<const float4*>(att1)[lane]);
    float4 a06 = make_float4(0.6f * a4.x, 0.6f * a4.y, 0.6f * a4.z, 0.6f * a4.w);
    float4 a04 = make_float4(0.4f * a4.x, 0.4f * a4.y, 0.4f * a4.z, 0.4f * a4.w);

    int beg = g_rowptr[dst];
    int end = g_rowptr[dst + 1];

    float  s0 = 0.f, s1 = 0.f, s2 = 0.f, s3 = 0.f;
    float4 A0 = {0,0,0,0}, A1 = {0,0,0,0}, A2 = {0,0,0,0}, A3 = {0,0,0,0};

    // self loop
    edge_step(dst, lane, xr4, a06, a04, s0, A0);

    int j = beg;
    for (; j + 4 <= end; j += 4) {
        int i0 = __ldg(&g_col[j]);
        int i1 = __ldg(&g_col[j + 1]);
        int i2 = __ldg(&g_col[j + 2]);
        int i3 = __ldg(&g_col[j + 3]);
        edge_step(i0, lane, xr4, a06, a04, s0, A0);
        edge_step(i1, lane, xr4, a06, a04, s1, A1);
        edge_step(i2, lane, xr4, a06, a04, s2, A2);
        edge_step(i3, lane, xr4, a06, a04, s3, A3);
    }
    for (; j < end; ++j)
        edge_step(__ldg(&g_col[j]), lane, xr4, a06, a04, s0, A0);

    float s = (s0 + s1) + (s2 + s3);
    float4 A;
    A.x = (A0.x + A1.x) + (A2.x + A3.x);
    A.y = (A0.y + A1.y) + (A2.y + A3.y);
    A.z = (A0.z + A1.z) + (A2.z + A3.z);
    A.w = (A0.w + A1.w) + (A2.w + A3.w);

    const float4 b4  = __ldg(&reinterpret_cast<const float4*>(b1)[lane]);
    const float4 wl4 = __ldg(&reinterpret_cast<const float4*>(Wl2)[lane]);
    const float4 wr4 = __ldg(&reinterpret_cast<const float4*>(Wr2)[lane]);

    float inv = 1.f / s;
    float ox = A.x * inv + b4.x;
    float oy = A.y * inv + b4.y;
    float oz = A.z * inv + b4.z;
    float ow = A.w * inv + b4.w;
    float hx = (ox > 0.f) ? ox : expm1f(ox);
    float hy = (oy > 0.f) ? oy : expm1f(oy);
    float hz = (oz > 0.f) ? oz : expm1f(oz);
    float hw = (ow > 0.f) ? ow : expm1f(ow);

    float l2 = warp_sum(hx * wl4.x + hy * wl4.y + hz * wl4.z + hw * wl4.w);
    float r2 = warp_sum(hx * wr4.x + hy * wr4.y + hz * wr4.z + hw * wr4.w);
    if (lane == 0) {
        g_xl2[dst] = l2;
        g_xr2[dst] = r2;
    }
}

// ---------------- Layer 2: 8-lane segments, 4 dsts per warp ----------------
__global__ __launch_bounds__(256) void agg2_k(const float* __restrict__ att2,
                                              const float* __restrict__ b2,
                                              float* __restrict__ out, int N) {
    int warpid = blockIdx.x * (blockDim.x >> 5) + (threadIdx.x >> 5);
    int lane = threadIdx.x & 31;
    int sub  = lane >> 3;
    int l8   = lane & 7;
    int dst0 = warpid * 4 + sub;
    int dst  = (dst0 < N) ? dst0 : (N - 1);

    float xr = g_xr2[dst];
    float a  = att2[0];
    int beg = g_rowptr[dst];
    int end = g_rowptr[dst + 1];

    float s = 0.f, w = 0.f;

    for (int j = beg + l8; j <= end; j += 8) {
        int src = (j < end) ? __ldg(&g_col[j]) : dst;
        float l = g_xl2[src];
        float t = l + xr;
        t = (t >= 0.f) ? t : 0.2f * t;
        float p = __expf(a * t);
        s += p;
        w += p * l;
    }

    s += __shfl_xor_sync(0xffffffffu, s, 4);
    s += __shfl_xor_sync(0xffffffffu, s, 2);
    s += __shfl_xor_sync(0xffffffffu, s, 1);
    w += __shfl_xor_sync(0xffffffffu, w, 4);
    w += __shfl_xor_sync(0xffffffffu, w, 2);
    w += __shfl_xor_sync(0xffffffffu, w, 1);

    if (l8 == 0 && dst0 < N) out[dst0] = w / s + b2[0];
}

// ---------------- launch ----------------
extern "C" void kernel_launch(void* const* d_in, const int* in_sizes, int n_in,
                              void* d_out, int out_size) {
    const float* x    = (const float*)d_in[0];
    const int*   ei   = (const int*)d_in[1];     // int32 (verified)
    const float* Wl1  = (const float*)d_in[2];
    const float* Wr1  = (const float*)d_in[3];
    const float* att1 = (const float*)d_in[4];
    const float* b1   = (const float*)d_in[5];
    const float* Wl2  = (const float*)d_in[6];
    const float* Wr2  = (const float*)d_in[7];
    const float* att2 = (const float*)d_in[8];
    const float* b2   = (const float*)d_in[9];
    float*       out  = (float*)d_out;

    int N = in_sizes[0] / F_IN;
    int E = in_sizes[1] / 2;
    int nsb = (N + 255) / 256;
    int gemm_blocks = (N + 63) / 64;
    int scat_blocks = (E + 1023) / 1024;

    hist_k<<<(E / 4 + 255) / 256, 256>>>(ei, E);
    scan_k<<<nsb, 256>>>(N, nsb);
    scatter_gemm_k<<<gemm_blocks + scat_blocks, 256>>>(x, Wl1, Wr1, ei, N, E, gemm_blocks);
    agg1_k<<<N, 32>>>(att1, b1, Wl2, Wr2, N);
    agg2_k<<<(N + 31) / 32, 256>>>(att2, b2, out, N);
}